// round 3
// baseline (speedup 1.0000x reference)
#include <cuda_runtime.h>
#include <cstdint>

// Gated delta rule recurrence: S_t = S_{t-1} @ A_t + B_t
// 128 CTAs (2 per chain, 32 rows each) x 128 threads, thread tile 2 rows x 8 cols.
// fp32 via packed fma.rn.f32x2. S kept in smem as DUPLICATED 8B entries (s,s),
// rows adjacent -> one LDS.128 per k yields both rows' broadcast operands.
// Fully unrolled k-loop with immediate-offset LDS: 11 instrs/k.
// 64 KB smem -> dynamic shared memory (static cap is 48 KB).

#define T_DIM 128
#define BH 64
#define D 64
#define ROWS 32
#define THREADS 128
#define TSTRIDE (BH * D * D)

#define A_FLOATS (D * D)            // 4096 floats = 16 KB per buffer
#define S_ULLS   (D * ROWS)         // 2048 ull    = 16 KB per buffer
#define SMEM_BYTES (2 * A_FLOATS * 4 + 2 * S_ULLS * 8)   // 65536

__device__ __forceinline__ uint32_t smem_u32(const void* p) {
    return (uint32_t)__cvta_generic_to_shared(p);
}
__device__ __forceinline__ unsigned long long pk2(float lo, float hi) {
    unsigned long long r;
    asm("mov.b64 %0,{%1,%2};" : "=l"(r) : "f"(lo), "f"(hi));
    return r;
}
__device__ __forceinline__ void upk2(unsigned long long v, float& lo, float& hi) {
    asm("mov.b64 {%0,%1},%2;" : "=f"(lo), "=f"(hi) : "l"(v));
}
__device__ __forceinline__ unsigned long long f2fma(unsigned long long a,
                                                    unsigned long long b,
                                                    unsigned long long c) {
    unsigned long long d;
    asm("fma.rn.f32x2 %0,%1,%2,%3;" : "=l"(d) : "l"(a), "l"(b), "l"(c));
    return d;
}

__global__ void __launch_bounds__(THREADS, 1) gdr_kernel(
    const float* __restrict__ A,
    const float* __restrict__ Bm,
    const float* __restrict__ S0,
    float* __restrict__ out)
{
    extern __shared__ char smem[];
    float* Abuf0 = (float*)smem;                                   // 16 KB
    float* Abuf1 = (float*)(smem + A_FLOATS * 4);                  // 16 KB
    unsigned long long* Sdup0 =
        (unsigned long long*)(smem + 2 * A_FLOATS * 4);            // 16 KB
    unsigned long long* Sdup1 = Sdup0 + S_ULLS;                    // 16 KB

    const int tid   = threadIdx.x;
    const int chain = blockIdx.x >> 1;
    const int half  = blockIdx.x & 1;
    const int r0base = half * ROWS;

    const int rg  = tid & 15;
    const int cg  = tid >> 4;
    const int j0  = cg * 8;
    const int rl0 = rg * 2;

    const long chainOff = (long)chain * (D * D);

    // ---- prologue: A[0] via cp.async ----
    {
        uint32_t s = smem_u32(Abuf0) + tid * 16;
        const float* g = A + chainOff + tid * 4;
        #pragma unroll
        for (int i = 0; i < 8; i++) {
            asm volatile("cp.async.cg.shared.global [%0],[%1],16;"
                         :: "r"(s + i * 2048), "l"(g + i * 512));
        }
        asm volatile("cp.async.commit_group;");
    }

    // Bm[0] -> registers
    float4 bm00, bm01, bm10, bm11;
    {
        const float* g = Bm + chainOff + (long)(r0base + rl0) * D + j0;
        bm00 = *(const float4*)(g);
        bm01 = *(const float4*)(g + 4);
        bm10 = *(const float4*)(g + D);
        bm11 = *(const float4*)(g + D + 4);
    }

    // Init Sdup0[k*ROWS + r] = (S0[r][k], S0[r][k])
    {
        int rl = tid & 31;
        int kb = (tid >> 5) * 16;
        const float* g = S0 + chainOff + (long)(r0base + rl) * D + kb;
        #pragma unroll
        for (int kk = 0; kk < 16; kk++) {
            float v = g[kk];
            Sdup0[(kb + kk) * ROWS + rl] = pk2(v, v);
        }
    }

    // ---- main time loop ----
    for (int t = 0; t < T_DIM; t++) {
        asm volatile("cp.async.wait_group 0;" ::: "memory");
        __syncthreads();   // publishes A[t] and Sdup[cur]

        const int cur = t & 1;
        float* Acur  = cur ? Abuf1 : Abuf0;
        float* Anext = cur ? Abuf0 : Abuf1;
        unsigned long long* Scur  = cur ? Sdup1 : Sdup0;
        unsigned long long* Snext = cur ? Sdup0 : Sdup1;

        // prefetch A[t+1]
        if (t + 1 < T_DIM) {
            uint32_t s = smem_u32(Anext) + tid * 16;
            const float* g = A + (long)(t + 1) * TSTRIDE + chainOff + tid * 4;
            #pragma unroll
            for (int i = 0; i < 8; i++) {
                asm volatile("cp.async.cg.shared.global [%0],[%1],16;"
                             :: "r"(s + i * 2048), "l"(g + i * 512));
            }
            asm volatile("cp.async.commit_group;");
        }

        // acc := Bm[t]
        unsigned long long a00, a01, a02, a03, a10, a11, a12, a13;
        a00 = pk2(bm00.x, bm00.y); a01 = pk2(bm00.z, bm00.w);
        a02 = pk2(bm01.x, bm01.y); a03 = pk2(bm01.z, bm01.w);
        a10 = pk2(bm10.x, bm10.y); a11 = pk2(bm10.z, bm10.w);
        a12 = pk2(bm11.x, bm11.y); a13 = pk2(bm11.z, bm11.w);

        // prefetch Bm[t+1] (overlaps k-loop)
        if (t + 1 < T_DIM) {
            const float* g = Bm + (long)(t + 1) * TSTRIDE + chainOff
                           + (long)(r0base + rl0) * D + j0;
            bm00 = *(const float4*)(g);
            bm01 = *(const float4*)(g + 4);
            bm10 = *(const float4*)(g + D);
            bm11 = *(const float4*)(g + D + 4);
        }

        // k-loop: immediate-offset LDS, 11 instrs per k
        const ulonglong2* __restrict__ Ap = (const ulonglong2*)(Acur + j0);
        const ulonglong2* __restrict__ Sp = (const ulonglong2*)(Scur + rl0);

        #pragma unroll
        for (int k = 0; k < D; k++) {
            ulonglong2 sv   = Sp[k * 16];      // (s_r0,s_r0),(s_r1,s_r1)
            ulonglong2 av01 = Ap[k * 16];      // A[k][j0..j0+3]
            ulonglong2 av23 = Ap[k * 16 + 1];  // A[k][j0+4..j0+7]
            a00 = f2fma(sv.x, av01.x, a00);
            a01 = f2fma(sv.x, av01.y, a01);
            a02 = f2fma(sv.x, av23.x, a02);
            a03 = f2fma(sv.x, av23.y, a03);
            a10 = f2fma(sv.y, av01.x, a10);
            a11 = f2fma(sv.y, av01.y, a11);
            a12 = f2fma(sv.y, av23.x, a12);
            a13 = f2fma(sv.y, av23.y, a13);
        }

        // epilogue
        float r0f[8], r1f[8];
        upk2(a00, r0f[0], r0f[1]); upk2(a01, r0f[2], r0f[3]);
        upk2(a02, r0f[4], r0f[5]); upk2(a03, r0f[6], r0f[7]);
        upk2(a10, r1f[0], r1f[1]); upk2(a11, r1f[2], r1f[3]);
        upk2(a12, r1f[4], r1f[5]); upk2(a13, r1f[6], r1f[7]);

        float* o = out + (long)t * TSTRIDE + chainOff
                 + (long)(r0base + rl0) * D + j0;
        *(float4*)(o)         = make_float4(r0f[0], r0f[1], r0f[2], r0f[3]);
        *(float4*)(o + 4)     = make_float4(r0f[4], r0f[5], r0f[6], r0f[7]);
        *(float4*)(o + D)     = make_float4(r1f[0], r1f[1], r1f[2], r1f[3]);
        *(float4*)(o + D + 4) = make_float4(r1f[4], r1f[5], r1f[6], r1f[7]);

        // Snew -> Sdup[next], duplicated pairs, both rows in one 16B store
        if (t + 1 < T_DIM) {
            #pragma unroll
            for (int jj = 0; jj < 8; jj++) {
                ulonglong2 w;
                w.x = pk2(r0f[jj], r0f[jj]);
                w.y = pk2(r1f[jj], r1f[jj]);
                *(ulonglong2*)&Snext[(j0 + jj) * ROWS + rl0] = w;
            }
        }
    }
}

extern "C" void kernel_launch(void* const* d_in, const int* in_sizes, int n_in,
                              void* d_out, int out_size) {
    const float* A  = (const float*)d_in[0];
    const float* Bm = (const float*)d_in[1];
    const float* S0 = (const float*)d_in[2];
    float* out = (float*)d_out;
    (void)in_sizes; (void)n_in; (void)out_size;

    cudaFuncSetAttribute(gdr_kernel,
                         cudaFuncAttributeMaxDynamicSharedMemorySize,
                         SMEM_BYTES);
    gdr_kernel<<<BH * 2, THREADS, SMEM_BYTES>>>(A, Bm, S0, out);
}